// round 15
// baseline (speedup 1.0000x reference)
#include <cuda_runtime.h>
#include <cuda_bf16.h>
#include <cstdint>

// Problem dims (fixed per reference)
#define BB   4
#define TT   2048
#define CC   1024
#define NH   16
#define HS   64
#define LL   256

// ---------------- scratch (device globals; no runtime allocation) ----------------
__device__ float g_tmp1[LL * LL];            // W_uq^T @ W_uk            (256,256)
__device__ float g_M[CC * LL];               // W_dq^T @ tmp1 (k_eff)    (1024,256)
__device__ float g_Vt[CC * LL];              // v_eff^T: Vt[d,l]         (1024,256)
__device__ float g_cq[BB * TT * LL];         // x @ W_dq^T               (8192,256)
__device__ float g_qf[(long long)BB * TT * CC];   // q_full  (8192,1024)
__device__ float g_kf[(long long)BB * TT * CC];   // KK_full (8192,1024)
__device__ float g_vf[(long long)BB * TT * CC];   // VV_full (8192,1024)

// ---------------- tf32 helpers ----------------
__device__ __forceinline__ float f2tff(float x) {
    uint32_t r;
    asm("cvt.rna.tf32.f32 %0, %1;" : "=r"(r) : "f"(x));
    return __uint_as_float(r);
}

__device__ __forceinline__ void mma_tf32(float* d, const uint32_t* a, const uint32_t* b) {
    asm volatile(
        "mma.sync.aligned.m16n8k8.row.col.f32.tf32.tf32.f32 "
        "{%0,%1,%2,%3},{%4,%5,%6,%7},{%8,%9},{%0,%1,%2,%3};\n"
        : "+f"(d[0]), "+f"(d[1]), "+f"(d[2]), "+f"(d[3])
        : "r"(a[0]), "r"(a[1]), "r"(a[2]), "r"(a[3]), "r"(b[0]), "r"(b[1]));
}

// ---------------- multi-op TF32 GEMM ----------------
// Up to 4 independent GEMMs in one launch; blockIdx.z selects the op.
// C[m,n] = sum_k A[m*sa_m + k*sa_k] * B[n*sb_n + k*sb_k]
// All ops in a launch share N, K (and BN). Per-op M; oversize y-blocks early-exit.
struct GOps {
    const float* A[4]; const float* B[4]; float* C[4];
    int M[4];
    long long sa_m[4], sa_k[4], sb_n[4], sb_k[4], sc_m[4];
};

template<int BN>
__global__ void __launch_bounds__(256)
gemm_multi(GOps ops, int N, int K)
{
    const int BM = 128, BK = 16, SA = 20, SB = 20;
    const int WN = BN / 2;
    const int NT = WN / 8;
    const int RBS = (BN * BK) / 256;
    const int RBV = RBS / 4;

    const int op = blockIdx.z;
    const int M = ops.M[op];
    const long long bm = (long long)blockIdx.y * BM;
    if (bm >= M) return;                     // oversize y-block for this op

    const float* __restrict__ A = ops.A[op];
    const float* __restrict__ B = ops.B[op];
    float* __restrict__ C = ops.C[op];
    const long long sa_m = ops.sa_m[op], sa_k = ops.sa_k[op];
    const long long sb_n = ops.sb_n[op], sb_k = ops.sb_k[op];
    const long long sc_m = ops.sc_m[op];

    __shared__ float As[2][BM * SA];
    __shared__ float Bs[2][BN * SB];

    const int t = threadIdx.x, lane = t & 31, wid = t >> 5;
    const int warp_m = wid & 3, warp_n = wid >> 2;
    const int rg = lane >> 2;
    const int tg = lane & 3;
    const long long bn = (long long)blockIdx.x * BN;

    const bool vecA = (sa_k == 1), vecB = (sb_k == 1);
    const int nk = K / BK;

    float acc[2][NT][4];
#pragma unroll
    for (int mt = 0; mt < 2; mt++)
#pragma unroll
        for (int nt = 0; nt < NT; nt++)
#pragma unroll
            for (int j = 0; j < 4; j++) acc[mt][nt][j] = 0.f;

    float ra[8], rb[RBS];

    auto loadA = [&](int kt) {
        long long k0 = (long long)kt * BK;
        if (vecA) {
#pragma unroll
            for (int i = 0; i < 2; i++) {
                int f = t + i * 256;
                int row = f >> 2, c4 = (f & 3) * 4;
                float4 v = *reinterpret_cast<const float4*>(&A[(bm + row) * sa_m + k0 + c4]);
                ra[i * 4 + 0] = v.x; ra[i * 4 + 1] = v.y;
                ra[i * 4 + 2] = v.z; ra[i * 4 + 3] = v.w;
            }
        } else {
#pragma unroll
            for (int i = 0; i < 8; i++) {
                int e = t + i * 256;
                int kk = e >> 7, row = e & 127;
                ra[i] = A[(bm + row) * sa_m + (k0 + kk) * sa_k];
            }
        }
    };
    auto storeA = [&](int buf) {
        if (vecA) {
#pragma unroll
            for (int i = 0; i < 2; i++) {
                int f = t + i * 256;
                int row = f >> 2, c4 = (f & 3) * 4;
                float* d = &As[buf][row * SA + c4];
#pragma unroll
                for (int j = 0; j < 4; j++) d[j] = f2tff(ra[i * 4 + j]);
            }
        } else {
#pragma unroll
            for (int i = 0; i < 8; i++) {
                int e = t + i * 256;
                int kk = e >> 7, row = e & 127;
                As[buf][row * SA + kk] = f2tff(ra[i]);
            }
        }
    };
    auto loadB = [&](int kt) {
        long long k0 = (long long)kt * BK;
        if (vecB) {
#pragma unroll
            for (int i = 0; i < RBV; i++) {
                int f = t + i * 256;
                int row = f >> 2, c4 = (f & 3) * 4;
                float4 v = *reinterpret_cast<const float4*>(&B[(bn + row) * sb_n + k0 + c4]);
                rb[i * 4 + 0] = v.x; rb[i * 4 + 1] = v.y;
                rb[i * 4 + 2] = v.z; rb[i * 4 + 3] = v.w;
            }
        } else {
#pragma unroll
            for (int i = 0; i < RBS; i++) {
                int e = t + i * 256;
                int kk = e / BN, n = e % BN;
                rb[i] = B[(bn + n) * sb_n + (k0 + kk) * sb_k];
            }
        }
    };
    auto storeB = [&](int buf) {
        if (vecB) {
#pragma unroll
            for (int i = 0; i < RBV; i++) {
                int f = t + i * 256;
                int row = f >> 2, c4 = (f & 3) * 4;
                float* d = &Bs[buf][row * SB + c4];
#pragma unroll
                for (int j = 0; j < 4; j++) d[j] = f2tff(rb[i * 4 + j]);
            }
        } else {
#pragma unroll
            for (int i = 0; i < RBS; i++) {
                int e = t + i * 256;
                int kk = e / BN, n = e % BN;
                Bs[buf][n * SB + kk] = f2tff(rb[i]);
            }
        }
    };

    auto compute = [&](int buf) {
#pragma unroll
        for (int ks = 0; ks < 2; ks++) {
            uint32_t af[2][4];
            const int ar = warp_m * 32 + rg;
            const int ac = ks * 8 + tg;
#pragma unroll
            for (int mt = 0; mt < 2; mt++) {
                const float* p = &As[buf][(ar + mt * 16) * SA + ac];
                af[mt][0] = __float_as_uint(p[0]);
                af[mt][1] = __float_as_uint(p[8 * SA]);
                af[mt][2] = __float_as_uint(p[4]);
                af[mt][3] = __float_as_uint(p[8 * SA + 4]);
            }
            uint32_t bf[NT][2];
            const int br = warp_n * WN + rg;
            const int bc = ks * 8 + tg;
#pragma unroll
            for (int nt = 0; nt < NT; nt++) {
                const float* p = &Bs[buf][(br + nt * 8) * SB + bc];
                bf[nt][0] = __float_as_uint(p[0]);
                bf[nt][1] = __float_as_uint(p[4]);
            }
#pragma unroll
            for (int mt = 0; mt < 2; mt++)
#pragma unroll
                for (int nt = 0; nt < NT; nt++)
                    mma_tf32(acc[mt][nt], af[mt], bf[nt]);
        }
    };

    loadA(0); loadB(0);
    storeA(0); storeB(0);
    __syncthreads();

    for (int kt = 0; kt < nk; kt++) {
        int buf = kt & 1;
        bool nxt = (kt + 1 < nk);
        if (nxt) { loadA(kt + 1); loadB(kt + 1); }
        compute(buf);
        if (nxt) { storeA(buf ^ 1); storeB(buf ^ 1); }
        __syncthreads();
    }

#pragma unroll
    for (int mt = 0; mt < 2; mt++) {
        long long gm0 = bm + warp_m * 32 + mt * 16 + rg;
#pragma unroll
        for (int nt = 0; nt < NT; nt++) {
            long long gn = bn + warp_n * WN + nt * 8 + tg * 2;
            float2 v0 = make_float2(acc[mt][nt][0], acc[mt][nt][1]);
            float2 v1 = make_float2(acc[mt][nt][2], acc[mt][nt][3]);
            *reinterpret_cast<float2*>(&C[gm0 * sc_m + gn]) = v0;
            *reinterpret_cast<float2*>(&C[(gm0 + 8) * sc_m + gn]) = v1;
        }
    }
}

// ---------------- TF32 flash attention, hs = 64 ----------------
// grid = (T/128, NH, B), 256 threads (8 warps). Warp w owns rows 16w..16w+15
// end-to-end: S mma -> register softmax (quad shuffles) -> P via smem -> PV mma.
// q/k/v live in full-width (B,T,NH*HS) layouts; rows have stride CC.
#define SQ 68
#define SK 68
#define SV 72
#define SP 68

#define FA2_SMEM_BYTES ((128 * SQ + 64 * SK + 64 * SV + 128 * SP) * 4)

__global__ void __launch_bounds__(256)
flash2(const float* __restrict__ qg, const float* __restrict__ kg,
       const float* __restrict__ vg, float* __restrict__ y)
{
    extern __shared__ float sh[];
    float* Qs = sh;               // 128 x SQ
    float* Ks = Qs + 128 * SQ;    // 64 x SK
    float* Vs = Ks + 64 * SK;     // 64 x SV
    float* Ps = Vs + 64 * SV;     // 128 x SP

    const int qb = (int)gridDim.x - 1 - (int)blockIdx.x;  // heavy blocks first
    const int h = blockIdx.y, b = blockIdx.z;
    const int t = threadIdx.x, lane = t & 31, w = t >> 5;
    const int rg = lane >> 2, tg = lane & 3;
    const int q0 = qb * 128;

    // stage Q (128 x 64), pre-scaled by 1/sqrt(hs)
    const float* qptr = qg + ((long long)b * TT + q0) * CC + h * HS;
#pragma unroll
    for (int i = 0; i < 8; i++) {
        int v = t + i * 256;
        int row = v >> 4, c = (v & 15) * 4;
        float4 x4 = *reinterpret_cast<const float4*>(&qptr[(long long)row * CC + c]);
        float* d = &Qs[row * SQ + c];
        d[0] = f2tff(x4.x * 0.125f); d[1] = f2tff(x4.y * 0.125f);
        d[2] = f2tff(x4.z * 0.125f); d[3] = f2tff(x4.w * 0.125f);
    }

    float m0 = -1e30f, m1 = -1e30f, l0 = 0.f, l1 = 0.f;
    float acc[8][4];
#pragma unroll
    for (int nt = 0; nt < 8; nt++)
#pragma unroll
        for (int j = 0; j < 4; j++) acc[nt][j] = 0.f;

    const float* kptr = kg + (long long)b * TT * CC + h * HS;
    const float* vptr = vg + (long long)b * TT * CC + h * HS;
    const int nkb = 2 * qb + 2;
    const int row_w = w * 16 + rg;

    for (int kb = 0; kb < nkb; kb++) {
        __syncthreads();   // K/V reuse barrier (also covers initial Q staging)
#pragma unroll
        for (int i = 0; i < 4; i++) {
            int v = t + i * 256;
            int row = v >> 4, c = (v & 15) * 4;
            float4 k4 = *reinterpret_cast<const float4*>(
                &kptr[((long long)kb * 64 + row) * CC + c]);
            float* dk = &Ks[row * SK + c];
            dk[0] = f2tff(k4.x); dk[1] = f2tff(k4.y);
            dk[2] = f2tff(k4.z); dk[3] = f2tff(k4.w);
            float4 v4 = *reinterpret_cast<const float4*>(
                &vptr[((long long)kb * 64 + row) * CC + c]);
            float* dv = &Vs[row * SV + c];
            dv[0] = f2tff(v4.x); dv[1] = f2tff(v4.y);
            dv[2] = f2tff(v4.z); dv[3] = f2tff(v4.w);
        }
        __syncthreads();

        // ---- S = Q @ K^T  (warp tile 16 x 64, K = 64) ----
        float s[8][4];
#pragma unroll
        for (int nt = 0; nt < 8; nt++)
#pragma unroll
            for (int j = 0; j < 4; j++) s[nt][j] = 0.f;

#pragma unroll
        for (int ks = 0; ks < 8; ks++) {
            const float* pa = &Qs[row_w * SQ + ks * 8 + tg];
            uint32_t af[4] = { __float_as_uint(pa[0]), __float_as_uint(pa[8 * SQ]),
                               __float_as_uint(pa[4]), __float_as_uint(pa[8 * SQ + 4]) };
#pragma unroll
            for (int nt = 0; nt < 8; nt++) {
                const float* pb = &Ks[(nt * 8 + rg) * SK + ks * 8 + tg];
                uint32_t bf[2] = { __float_as_uint(pb[0]), __float_as_uint(pb[4]) };
                mma_tf32(s[nt], af, bf);
            }
        }

        // causal mask (only the last two key blocks can clip)
        if (kb >= 2 * qb) {
            int rgl = q0 + row_w;
#pragma unroll
            for (int nt = 0; nt < 8; nt++) {
                int c0 = kb * 64 + nt * 8 + 2 * tg;
                if (c0     > rgl)     s[nt][0] = -1e30f;
                if (c0 + 1 > rgl)     s[nt][1] = -1e30f;
                if (c0     > rgl + 8) s[nt][2] = -1e30f;
                if (c0 + 1 > rgl + 8) s[nt][3] = -1e30f;
            }
        }

        // ---- register online softmax (rows rg, rg+8 per thread; quad reduce) ----
        float vx0 = -1e30f, vx1 = -1e30f;
#pragma unroll
        for (int nt = 0; nt < 8; nt++) {
            vx0 = fmaxf(vx0, fmaxf(s[nt][0], s[nt][1]));
            vx1 = fmaxf(vx1, fmaxf(s[nt][2], s[nt][3]));
        }
        vx0 = fmaxf(vx0, __shfl_xor_sync(0xffffffffu, vx0, 1));
        vx0 = fmaxf(vx0, __shfl_xor_sync(0xffffffffu, vx0, 2));
        vx1 = fmaxf(vx1, __shfl_xor_sync(0xffffffffu, vx1, 1));
        vx1 = fmaxf(vx1, __shfl_xor_sync(0xffffffffu, vx1, 2));

        float mn0 = fmaxf(m0, vx0), mn1 = fmaxf(m1, vx1);
        float al0 = __expf(m0 - mn0), al1 = __expf(m1 - mn1);
        m0 = mn0; m1 = mn1;

        float sum0 = 0.f, sum1 = 0.f;
#pragma unroll
        for (int nt = 0; nt < 8; nt++) {
            float p00 = __expf(s[nt][0] - m0);
            float p01 = __expf(s[nt][1] - m0);
            float p10 = __expf(s[nt][2] - m1);
            float p11 = __expf(s[nt][3] - m1);
            sum0 += p00 + p01;
            sum1 += p10 + p11;
            int cc = nt * 8 + 2 * tg;
            Ps[row_w * SP + cc]           = f2tff(p00);
            Ps[row_w * SP + cc + 1]       = f2tff(p01);
            Ps[(row_w + 8) * SP + cc]     = f2tff(p10);
            Ps[(row_w + 8) * SP + cc + 1] = f2tff(p11);
        }
        sum0 += __shfl_xor_sync(0xffffffffu, sum0, 1);
        sum0 += __shfl_xor_sync(0xffffffffu, sum0, 2);
        sum1 += __shfl_xor_sync(0xffffffffu, sum1, 1);
        sum1 += __shfl_xor_sync(0xffffffffu, sum1, 2);
        l0 = l0 * al0 + sum0;
        l1 = l1 * al1 + sum1;

#pragma unroll
        for (int nt = 0; nt < 8; nt++) {
            acc[nt][0] *= al0; acc[nt][1] *= al0;
            acc[nt][2] *= al1; acc[nt][3] *= al1;
        }
        __syncwarp();

        // ---- PV: acc(16 x 64) += P(16 x 64) @ V(64 x 64) ----
#pragma unroll
        for (int ks = 0; ks < 8; ks++) {
            const float* pa = &Ps[row_w * SP + ks * 8 + tg];
            uint32_t af[4] = { __float_as_uint(pa[0]), __float_as_uint(pa[8 * SP]),
                               __float_as_uint(pa[4]), __float_as_uint(pa[8 * SP + 4]) };
#pragma unroll
            for (int nt = 0; nt < 8; nt++) {
                const float* pb = &Vs[(ks * 8 + tg) * SV + nt * 8 + rg];
                uint32_t bf[2] = { __float_as_uint(pb[0]), __float_as_uint(pb[4 * SV]) };
                mma_tf32(acc[nt], af, bf);
            }
        }
    }

    // ---- epilogue: normalize and write y[b, t, h*64 + d] ----
    float il0 = 1.f / l0, il1 = 1.f / l1;
    float* op = y + ((long long)b * TT + q0 + row_w) * CC + h * HS;
#pragma unroll
    for (int nt = 0; nt < 8; nt++) {
        int cc = nt * 8 + 2 * tg;
        *reinterpret_cast<float2*>(&op[cc]) =
            make_float2(acc[nt][0] * il0, acc[nt][1] * il0);
        *reinterpret_cast<float2*>(&op[(long long)CC * 8 + cc]) =
            make_float2(acc[nt][2] * il1, acc[nt][3] * il1);
    }
}

// ---------------- launch ----------------
extern "C" void kernel_launch(void* const* d_in, const int* in_sizes, int n_in,
                              void* d_out, int out_size)
{
    const float* x     = (const float*)d_in[0];   // (4,2048,1024)
    const float* W_dq  = (const float*)d_in[1];   // (256,1024)
    const float* W_uq  = (const float*)d_in[2];   // (1024,256)
    const float* W_dkv = (const float*)d_in[3];   // (256,1024)
    const float* W_uk  = (const float*)d_in[4];   // (1024,256)
    const float* W_uv  = (const float*)d_in[5];   // (1024,256)
    const float* W_o   = (const float*)d_in[6];   // (1024,1024)

    float* y   = (float*)d_out;                    // (4,2048,1024)
    float* ckv = y + (long long)BB * TT * CC;      // (4,2048,256)

    float *p_tmp1, *p_M, *p_Vt, *p_cq, *p_qf, *p_kf, *p_vf;
    cudaGetSymbolAddress((void**)&p_tmp1, g_tmp1);
    cudaGetSymbolAddress((void**)&p_M,    g_M);
    cudaGetSymbolAddress((void**)&p_Vt,   g_Vt);
    cudaGetSymbolAddress((void**)&p_cq,   g_cq);
    cudaGetSymbolAddress((void**)&p_qf,   g_qf);
    cudaGetSymbolAddress((void**)&p_kf,   g_kf);
    cudaGetSymbolAddress((void**)&p_vf,   g_vf);

    dim3 thr(256);

    // ---- Launch C: 4 independent ops, N=256, K=1024 ----
    //  op0: cq   = x @ W_dq^T                       (8192 x 256)
    //  op1: ckv  = x @ W_dkv^T   -> output region   (8192 x 256)
    //  op2: Vt[d,l] = sum_c W_o[d,c] W_uv[c,l]      (1024 x 256)
    //  op3: tmp1[i,j] = sum_c W_uq[c,i] W_uk[c,j]   ( 256 x 256)
    {
        GOps o = {};
        o.A[0] = x;     o.B[0] = W_dq;  o.C[0] = p_cq;   o.M[0] = 8192;
        o.sa_m[0] = 1024; o.sa_k[0] = 1; o.sb_n[0] = 1024; o.sb_k[0] = 1; o.sc_m[0] = 256;
        o.A[1] = x;     o.B[1] = W_dkv; o.C[1] = ckv;    o.M[1] = 8192;
        o.sa_m[1] = 1024; o.sa_k[1] = 1; o.sb_n[1] = 1024; o.sb_k[1] = 1; o.sc_m[1] = 256;
        o.A[2] = W_o;   o.B[2] = W_uv;  o.C[2] = p_Vt;   o.M[2] = 1024;
        o.sa_m[2] = 1024; o.sa_k[2] = 1; o.sb_n[2] = 1;    o.sb_k[2] = 256; o.sc_m[2] = 256;
        o.A[3] = W_uq;  o.B[3] = W_uk;  o.C[3] = p_tmp1; o.M[3] = 256;
        o.sa_m[3] = 1;  o.sa_k[3] = 256; o.sb_n[3] = 1;   o.sb_k[3] = 256; o.sc_m[3] = 256;
        gemm_multi<128><<<dim3(2, 64, 4), thr>>>(o, 256, 1024);
    }

    // ---- Launch B: M[c,j] = sum_i W_dq[i,c] tmp1[i,j]   (1024 x 256, K=256) ----
    {
        GOps o = {};
        o.A[0] = W_dq; o.B[0] = p_tmp1; o.C[0] = p_M; o.M[0] = 1024;
        o.sa_m[0] = 1; o.sa_k[0] = 1024; o.sb_n[0] = 1; o.sb_k[0] = 256; o.sc_m[0] = 256;
        gemm_multi<128><<<dim3(2, 8, 1), thr>>>(o, 256, 256);
    }

    // ---- Launch D: 3 full-width head GEMMs, M=8192, N=1024, K=256 ----
    //  op0: q_full  = cq  @ W_uq^T
    //  op1: KK_full = ckv @ M^T
    //  op2: VV_full = ckv @ Vt^T
    {
        GOps o = {};
        o.A[0] = p_cq; o.B[0] = W_uq; o.C[0] = p_qf; o.M[0] = 8192;
        o.sa_m[0] = 256; o.sa_k[0] = 1; o.sb_n[0] = 256; o.sb_k[0] = 1; o.sc_m[0] = 1024;
        o.A[1] = ckv;  o.B[1] = p_M;  o.C[1] = p_kf; o.M[1] = 8192;
        o.sa_m[1] = 256; o.sa_k[1] = 1; o.sb_n[1] = 256; o.sb_k[1] = 1; o.sc_m[1] = 1024;
        o.A[2] = ckv;  o.B[2] = p_Vt; o.C[2] = p_vf; o.M[2] = 8192;
        o.sa_m[2] = 256; o.sa_k[2] = 1; o.sb_n[2] = 256; o.sb_k[2] = 1; o.sc_m[2] = 1024;
        gemm_multi<128><<<dim3(8, 64, 3), thr>>>(o, 1024, 256);
    }

    // ---- flash attention (hs=64), writes y head-slices directly ----
    cudaFuncSetAttribute(flash2, cudaFuncAttributeMaxDynamicSharedMemorySize,
                         FA2_SMEM_BYTES);
    flash2<<<dim3(TT / 128, NH, BB), thr, FA2_SMEM_BYTES>>>(p_qf, p_kf, p_vf, y);
}

// round 16
// speedup vs baseline: 1.0092x; 1.0092x over previous
#include <cuda_runtime.h>
#include <cuda_bf16.h>
#include <cstdint>

// Problem dims (fixed per reference)
#define BB   4
#define TT   2048
#define CC   1024
#define NH   16
#define HS   64
#define LL   256

// ---------------- scratch (device globals; no runtime allocation) ----------------
__device__ float g_tmp1[LL * LL];            // W_uq^T @ W_uk            (256,256)
__device__ float g_M[CC * LL];               // W_dq^T @ tmp1 (k_eff)    (1024,256)
__device__ float g_Vt[CC * LL];              // v_eff^T: Vt[d,l]         (1024,256)
__device__ float g_cq[BB * TT * LL];         // x @ W_dq^T               (8192,256)
__device__ float g_qf[(long long)BB * TT * CC];   // q_full  (8192,1024)
__device__ float g_kf[(long long)BB * TT * CC];   // KK_full (8192,1024)
__device__ float g_vf[(long long)BB * TT * CC];   // VV_full (8192,1024)

// ---------------- tf32 helpers ----------------
__device__ __forceinline__ float f2tff(float x) {
    uint32_t r;
    asm("cvt.rna.tf32.f32 %0, %1;" : "=r"(r) : "f"(x));
    return __uint_as_float(r);
}

__device__ __forceinline__ void mma_tf32(float* d, const uint32_t* a, const uint32_t* b) {
    asm volatile(
        "mma.sync.aligned.m16n8k8.row.col.f32.tf32.tf32.f32 "
        "{%0,%1,%2,%3},{%4,%5,%6,%7},{%8,%9},{%0,%1,%2,%3};\n"
        : "+f"(d[0]), "+f"(d[1]), "+f"(d[2]), "+f"(d[3])
        : "r"(a[0]), "r"(a[1]), "r"(a[2]), "r"(a[3]), "r"(b[0]), "r"(b[1]));
}

// ---------------- multi-op TF32 GEMM ----------------
// Up to 4 independent GEMMs in one launch; blockIdx.z selects the op.
// C[m,n] = sum_k A[m*sa_m + k*sa_k] * B[n*sb_n + k*sb_k]
// All ops in a launch share N, K (and BN). Per-op M; oversize y-blocks early-exit.
struct GOps {
    const float* A[4]; const float* B[4]; float* C[4];
    int M[4];
    long long sa_m[4], sa_k[4], sb_n[4], sb_k[4], sc_m[4];
};

template<int BN>
__global__ void __launch_bounds__(256)
gemm_multi(GOps ops, int N, int K)
{
    const int BM = 128, BK = 16, SA = 20, SB = 20;
    const int WN = BN / 2;
    const int NT = WN / 8;
    const int RBS = (BN * BK) / 256;
    const int RBV = RBS / 4;

    const int op = blockIdx.z;
    const int M = ops.M[op];
    const long long bm = (long long)blockIdx.y * BM;
    if (bm >= M) return;                     // oversize y-block for this op

    const float* __restrict__ A = ops.A[op];
    const float* __restrict__ B = ops.B[op];
    float* __restrict__ C = ops.C[op];
    const long long sa_m = ops.sa_m[op], sa_k = ops.sa_k[op];
    const long long sb_n = ops.sb_n[op], sb_k = ops.sb_k[op];
    const long long sc_m = ops.sc_m[op];

    __shared__ float As[2][BM * SA];
    __shared__ float Bs[2][BN * SB];

    const int t = threadIdx.x, lane = t & 31, wid = t >> 5;
    const int warp_m = wid & 3, warp_n = wid >> 2;
    const int rg = lane >> 2;
    const int tg = lane & 3;
    const long long bn = (long long)blockIdx.x * BN;

    const bool vecA = (sa_k == 1), vecB = (sb_k == 1);
    const int nk = K / BK;

    float acc[2][NT][4];
#pragma unroll
    for (int mt = 0; mt < 2; mt++)
#pragma unroll
        for (int nt = 0; nt < NT; nt++)
#pragma unroll
            for (int j = 0; j < 4; j++) acc[mt][nt][j] = 0.f;

    float ra[8], rb[RBS];

    auto loadA = [&](int kt) {
        long long k0 = (long long)kt * BK;
        if (vecA) {
#pragma unroll
            for (int i = 0; i < 2; i++) {
                int f = t + i * 256;
                int row = f >> 2, c4 = (f & 3) * 4;
                float4 v = *reinterpret_cast<const float4*>(&A[(bm + row) * sa_m + k0 + c4]);
                ra[i * 4 + 0] = v.x; ra[i * 4 + 1] = v.y;
                ra[i * 4 + 2] = v.z; ra[i * 4 + 3] = v.w;
            }
        } else {
#pragma unroll
            for (int i = 0; i < 8; i++) {
                int e = t + i * 256;
                int kk = e >> 7, row = e & 127;
                ra[i] = A[(bm + row) * sa_m + (k0 + kk) * sa_k];
            }
        }
    };
    auto storeA = [&](int buf) {
        if (vecA) {
#pragma unroll
            for (int i = 0; i < 2; i++) {
                int f = t + i * 256;
                int row = f >> 2, c4 = (f & 3) * 4;
                float* d = &As[buf][row * SA + c4];
#pragma unroll
                for (int j = 0; j < 4; j++) d[j] = f2tff(ra[i * 4 + j]);
            }
        } else {
#pragma unroll
            for (int i = 0; i < 8; i++) {
                int e = t + i * 256;
                int kk = e >> 7, row = e & 127;
                As[buf][row * SA + kk] = f2tff(ra[i]);
            }
        }
    };
    auto loadB = [&](int kt) {
        long long k0 = (long long)kt * BK;
        if (vecB) {
#pragma unroll
            for (int i = 0; i < RBV; i++) {
                int f = t + i * 256;
                int row = f >> 2, c4 = (f & 3) * 4;
                float4 v = *reinterpret_cast<const float4*>(&B[(bn + row) * sb_n + k0 + c4]);
                rb[i * 4 + 0] = v.x; rb[i * 4 + 1] = v.y;
                rb[i * 4 + 2] = v.z; rb[i * 4 + 3] = v.w;
            }
        } else {
#pragma unroll
            for (int i = 0; i < RBS; i++) {
                int e = t + i * 256;
                int kk = e / BN, n = e % BN;
                rb[i] = B[(bn + n) * sb_n + (k0 + kk) * sb_k];
            }
        }
    };
    auto storeB = [&](int buf) {
        if (vecB) {
#pragma unroll
            for (int i = 0; i < RBV; i++) {
                int f = t + i * 256;
                int row = f >> 2, c4 = (f & 3) * 4;
                float* d = &Bs[buf][row * SB + c4];
#pragma unroll
                for (int j = 0; j < 4; j++) d[j] = f2tff(rb[i * 4 + j]);
            }
        } else {
#pragma unroll
            for (int i = 0; i < RBS; i++) {
                int e = t + i * 256;
                int kk = e / BN, n = e % BN;
                Bs[buf][n * SB + kk] = f2tff(rb[i]);
            }
        }
    };

    auto compute = [&](int buf) {
#pragma unroll
        for (int ks = 0; ks < 2; ks++) {
            uint32_t af[2][4];
            const int ar = warp_m * 32 + rg;
            const int ac = ks * 8 + tg;
#pragma unroll
            for (int mt = 0; mt < 2; mt++) {
                const float* p = &As[buf][(ar + mt * 16) * SA + ac];
                af[mt][0] = __float_as_uint(p[0]);
                af[mt][1] = __float_as_uint(p[8 * SA]);
                af[mt][2] = __float_as_uint(p[4]);
                af[mt][3] = __float_as_uint(p[8 * SA + 4]);
            }
            uint32_t bf[NT][2];
            const int br = warp_n * WN + rg;
            const int bc = ks * 8 + tg;
#pragma unroll
            for (int nt = 0; nt < NT; nt++) {
                const float* p = &Bs[buf][(br + nt * 8) * SB + bc];
                bf[nt][0] = __float_as_uint(p[0]);
                bf[nt][1] = __float_as_uint(p[4]);
            }
#pragma unroll
            for (int mt = 0; mt < 2; mt++)
#pragma unroll
                for (int nt = 0; nt < NT; nt++)
                    mma_tf32(acc[mt][nt], af[mt], bf[nt]);
        }
    };

    loadA(0); loadB(0);
    storeA(0); storeB(0);
    __syncthreads();

    for (int kt = 0; kt < nk; kt++) {
        int buf = kt & 1;
        bool nxt = (kt + 1 < nk);
        if (nxt) { loadA(kt + 1); loadB(kt + 1); }
        compute(buf);
        if (nxt) { storeA(buf ^ 1); storeB(buf ^ 1); }
        __syncthreads();
    }

#pragma unroll
    for (int mt = 0; mt < 2; mt++) {
        long long gm0 = bm + warp_m * 32 + mt * 16 + rg;
#pragma unroll
        for (int nt = 0; nt < NT; nt++) {
            long long gn = bn + warp_n * WN + nt * 8 + tg * 2;
            float2 v0 = make_float2(acc[mt][nt][0], acc[mt][nt][1]);
            float2 v1 = make_float2(acc[mt][nt][2], acc[mt][nt][3]);
            *reinterpret_cast<float2*>(&C[gm0 * sc_m + gn]) = v0;
            *reinterpret_cast<float2*>(&C[(gm0 + 8) * sc_m + gn]) = v1;
        }
    }
}

// ---------------- TF32 flash attention, hs = 64 ----------------
// grid = (T/128, NH, B), 256 threads (8 warps). Warp w owns rows 16w..16w+15
// end-to-end: S mma -> register softmax (quad shuffles) -> P via smem -> PV mma.
// q/k/v live in full-width (B,T,NH*HS) layouts; rows have stride CC.
#define SQ 68
#define SK 68
#define SV 72
#define SP 68

#define FA2_SMEM_BYTES ((128 * SQ + 64 * SK + 64 * SV + 128 * SP) * 4)

__global__ void __launch_bounds__(256)
flash2(const float* __restrict__ qg, const float* __restrict__ kg,
       const float* __restrict__ vg, float* __restrict__ y)
{
    extern __shared__ float sh[];
    float* Qs = sh;               // 128 x SQ
    float* Ks = Qs + 128 * SQ;    // 64 x SK
    float* Vs = Ks + 64 * SK;     // 64 x SV
    float* Ps = Vs + 64 * SV;     // 128 x SP

    const int qb = (int)gridDim.x - 1 - (int)blockIdx.x;  // heavy blocks first
    const int h = blockIdx.y, b = blockIdx.z;
    const int t = threadIdx.x, lane = t & 31, w = t >> 5;
    const int rg = lane >> 2, tg = lane & 3;
    const int q0 = qb * 128;

    // stage Q (128 x 64), pre-scaled by 1/sqrt(hs)
    const float* qptr = qg + ((long long)b * TT + q0) * CC + h * HS;
#pragma unroll
    for (int i = 0; i < 8; i++) {
        int v = t + i * 256;
        int row = v >> 4, c = (v & 15) * 4;
        float4 x4 = *reinterpret_cast<const float4*>(&qptr[(long long)row * CC + c]);
        float* d = &Qs[row * SQ + c];
        d[0] = f2tff(x4.x * 0.125f); d[1] = f2tff(x4.y * 0.125f);
        d[2] = f2tff(x4.z * 0.125f); d[3] = f2tff(x4.w * 0.125f);
    }

    float m0 = -1e30f, m1 = -1e30f, l0 = 0.f, l1 = 0.f;
    float acc[8][4];
#pragma unroll
    for (int nt = 0; nt < 8; nt++)
#pragma unroll
        for (int j = 0; j < 4; j++) acc[nt][j] = 0.f;

    const float* kptr = kg + (long long)b * TT * CC + h * HS;
    const float* vptr = vg + (long long)b * TT * CC + h * HS;
    const int nkb = 2 * qb + 2;
    const int row_w = w * 16 + rg;

    for (int kb = 0; kb < nkb; kb++) {
        __syncthreads();   // K/V reuse barrier (also covers initial Q staging)
#pragma unroll
        for (int i = 0; i < 4; i++) {
            int v = t + i * 256;
            int row = v >> 4, c = (v & 15) * 4;
            float4 k4 = *reinterpret_cast<const float4*>(
                &kptr[((long long)kb * 64 + row) * CC + c]);
            float* dk = &Ks[row * SK + c];
            dk[0] = f2tff(k4.x); dk[1] = f2tff(k4.y);
            dk[2] = f2tff(k4.z); dk[3] = f2tff(k4.w);
            float4 v4 = *reinterpret_cast<const float4*>(
                &vptr[((long long)kb * 64 + row) * CC + c]);
            float* dv = &Vs[row * SV + c];
            dv[0] = f2tff(v4.x); dv[1] = f2tff(v4.y);
            dv[2] = f2tff(v4.z); dv[3] = f2tff(v4.w);
        }
        __syncthreads();

        // ---- S = Q @ K^T  (warp tile 16 x 64, K = 64) ----
        float s[8][4];
#pragma unroll
        for (int nt = 0; nt < 8; nt++)
#pragma unroll
            for (int j = 0; j < 4; j++) s[nt][j] = 0.f;

#pragma unroll
        for (int ks = 0; ks < 8; ks++) {
            const float* pa = &Qs[row_w * SQ + ks * 8 + tg];
            uint32_t af[4] = { __float_as_uint(pa[0]), __float_as_uint(pa[8 * SQ]),
                               __float_as_uint(pa[4]), __float_as_uint(pa[8 * SQ + 4]) };
#pragma unroll
            for (int nt = 0; nt < 8; nt++) {
                const float* pb = &Ks[(nt * 8 + rg) * SK + ks * 8 + tg];
                uint32_t bf[2] = { __float_as_uint(pb[0]), __float_as_uint(pb[4]) };
                mma_tf32(s[nt], af, bf);
            }
        }

        // causal mask (only the last two key blocks can clip)
        if (kb >= 2 * qb) {
            int rgl = q0 + row_w;
#pragma unroll
            for (int nt = 0; nt < 8; nt++) {
                int c0 = kb * 64 + nt * 8 + 2 * tg;
                if (c0     > rgl)     s[nt][0] = -1e30f;
                if (c0 + 1 > rgl)     s[nt][1] = -1e30f;
                if (c0     > rgl + 8) s[nt][2] = -1e30f;
                if (c0 + 1 > rgl + 8) s[nt][3] = -1e30f;
            }
        }

        // ---- register online softmax (rows rg, rg+8 per thread; quad reduce) ----
        float vx0 = -1e30f, vx1 = -1e30f;
#pragma unroll
        for (int nt = 0; nt < 8; nt++) {
            vx0 = fmaxf(vx0, fmaxf(s[nt][0], s[nt][1]));
            vx1 = fmaxf(vx1, fmaxf(s[nt][2], s[nt][3]));
        }
        vx0 = fmaxf(vx0, __shfl_xor_sync(0xffffffffu, vx0, 1));
        vx0 = fmaxf(vx0, __shfl_xor_sync(0xffffffffu, vx0, 2));
        vx1 = fmaxf(vx1, __shfl_xor_sync(0xffffffffu, vx1, 1));
        vx1 = fmaxf(vx1, __shfl_xor_sync(0xffffffffu, vx1, 2));

        float mn0 = fmaxf(m0, vx0), mn1 = fmaxf(m1, vx1);
        float al0 = __expf(m0 - mn0), al1 = __expf(m1 - mn1);
        m0 = mn0; m1 = mn1;

        float sum0 = 0.f, sum1 = 0.f;
#pragma unroll
        for (int nt = 0; nt < 8; nt++) {
            float p00 = __expf(s[nt][0] - m0);
            float p01 = __expf(s[nt][1] - m0);
            float p10 = __expf(s[nt][2] - m1);
            float p11 = __expf(s[nt][3] - m1);
            sum0 += p00 + p01;
            sum1 += p10 + p11;
            int cc = nt * 8 + 2 * tg;
            Ps[row_w * SP + cc]           = f2tff(p00);
            Ps[row_w * SP + cc + 1]       = f2tff(p01);
            Ps[(row_w + 8) * SP + cc]     = f2tff(p10);
            Ps[(row_w + 8) * SP + cc + 1] = f2tff(p11);
        }
        sum0 += __shfl_xor_sync(0xffffffffu, sum0, 1);
        sum0 += __shfl_xor_sync(0xffffffffu, sum0, 2);
        sum1 += __shfl_xor_sync(0xffffffffu, sum1, 1);
        sum1 += __shfl_xor_sync(0xffffffffu, sum1, 2);
        l0 = l0 * al0 + sum0;
        l1 = l1 * al1 + sum1;

#pragma unroll
        for (int nt = 0; nt < 8; nt++) {
            acc[nt][0] *= al0; acc[nt][1] *= al0;
            acc[nt][2] *= al1; acc[nt][3] *= al1;
        }
        __syncwarp();

        // ---- PV: acc(16 x 64) += P(16 x 64) @ V(64 x 64) ----
#pragma unroll
        for (int ks = 0; ks < 8; ks++) {
            const float* pa = &Ps[row_w * SP + ks * 8 + tg];
            uint32_t af[4] = { __float_as_uint(pa[0]), __float_as_uint(pa[8 * SP]),
                               __float_as_uint(pa[4]), __float_as_uint(pa[8 * SP + 4]) };
#pragma unroll
            for (int nt = 0; nt < 8; nt++) {
                const float* pb = &Vs[(ks * 8 + tg) * SV + nt * 8 + rg];
                uint32_t bf[2] = { __float_as_uint(pb[0]), __float_as_uint(pb[4 * SV]) };
                mma_tf32(acc[nt], af, bf);
            }
        }
    }

    // ---- epilogue: normalize and write y[b, t, h*64 + d] ----
    float il0 = 1.f / l0, il1 = 1.f / l1;
    float* op = y + ((long long)b * TT + q0 + row_w) * CC + h * HS;
#pragma unroll
    for (int nt = 0; nt < 8; nt++) {
        int cc = nt * 8 + 2 * tg;
        *reinterpret_cast<float2*>(&op[cc]) =
            make_float2(acc[nt][0] * il0, acc[nt][1] * il0);
        *reinterpret_cast<float2*>(&op[(long long)CC * 8 + cc]) =
            make_float2(acc[nt][2] * il1, acc[nt][3] * il1);
    }
}

// ---------------- launch ----------------
extern "C" void kernel_launch(void* const* d_in, const int* in_sizes, int n_in,
                              void* d_out, int out_size)
{
    const float* x     = (const float*)d_in[0];   // (4,2048,1024)
    const float* W_dq  = (const float*)d_in[1];   // (256,1024)
    const float* W_uq  = (const float*)d_in[2];   // (1024,256)
    const float* W_dkv = (const float*)d_in[3];   // (256,1024)
    const float* W_uk  = (const float*)d_in[4];   // (1024,256)
    const float* W_uv  = (const float*)d_in[5];   // (1024,256)
    const float* W_o   = (const float*)d_in[6];   // (1024,1024)

    float* y   = (float*)d_out;                    // (4,2048,1024)
    float* ckv = y + (long long)BB * TT * CC;      // (4,2048,256)

    float *p_tmp1, *p_M, *p_Vt, *p_cq, *p_qf, *p_kf, *p_vf;
    cudaGetSymbolAddress((void**)&p_tmp1, g_tmp1);
    cudaGetSymbolAddress((void**)&p_M,    g_M);
    cudaGetSymbolAddress((void**)&p_Vt,   g_Vt);
    cudaGetSymbolAddress((void**)&p_cq,   g_cq);
    cudaGetSymbolAddress((void**)&p_qf,   g_qf);
    cudaGetSymbolAddress((void**)&p_kf,   g_kf);
    cudaGetSymbolAddress((void**)&p_vf,   g_vf);

    dim3 thr(256);

    // ---- Launch C: 4 independent ops, N=256, K=1024 ----
    //  op0: cq   = x @ W_dq^T                       (8192 x 256)
    //  op1: ckv  = x @ W_dkv^T   -> output region   (8192 x 256)
    //  op2: Vt[d,l] = sum_c W_o[d,c] W_uv[c,l]      (1024 x 256)
    //  op3: tmp1[i,j] = sum_c W_uq[c,i] W_uk[c,j]   ( 256 x 256)
    {
        GOps o = {};
        o.A[0] = x;     o.B[0] = W_dq;  o.C[0] = p_cq;   o.M[0] = 8192;
        o.sa_m[0] = 1024; o.sa_k[0] = 1; o.sb_n[0] = 1024; o.sb_k[0] = 1; o.sc_m[0] = 256;
        o.A[1] = x;     o.B[1] = W_dkv; o.C[1] = ckv;    o.M[1] = 8192;
        o.sa_m[1] = 1024; o.sa_k[1] = 1; o.sb_n[1] = 1024; o.sb_k[1] = 1; o.sc_m[1] = 256;
        o.A[2] = W_o;   o.B[2] = W_uv;  o.C[2] = p_Vt;   o.M[2] = 1024;
        o.sa_m[2] = 1024; o.sa_k[2] = 1; o.sb_n[2] = 1;    o.sb_k[2] = 256; o.sc_m[2] = 256;
        o.A[3] = W_uq;  o.B[3] = W_uk;  o.C[3] = p_tmp1; o.M[3] = 256;
        o.sa_m[3] = 1;  o.sa_k[3] = 256; o.sb_n[3] = 1;   o.sb_k[3] = 256; o.sc_m[3] = 256;
        gemm_multi<128><<<dim3(2, 64, 4), thr>>>(o, 256, 1024);
    }

    // ---- Launch B: M[c,j] = sum_i W_dq[i,c] tmp1[i,j]   (1024 x 256, K=256) ----
    {
        GOps o = {};
        o.A[0] = W_dq; o.B[0] = p_tmp1; o.C[0] = p_M; o.M[0] = 1024;
        o.sa_m[0] = 1; o.sa_k[0] = 1024; o.sb_n[0] = 1; o.sb_k[0] = 256; o.sc_m[0] = 256;
        gemm_multi<128><<<dim3(2, 8, 1), thr>>>(o, 256, 256);
    }

    // ---- Launch D: 3 full-width head GEMMs, M=8192, N=1024, K=256 ----
    //  op0: q_full  = cq  @ W_uq^T
    //  op1: KK_full = ckv @ M^T
    //  op2: VV_full = ckv @ Vt^T
    {
        GOps o = {};
        o.A[0] = p_cq; o.B[0] = W_uq; o.C[0] = p_qf; o.M[0] = 8192;
        o.sa_m[0] = 256; o.sa_k[0] = 1; o.sb_n[0] = 256; o.sb_k[0] = 1; o.sc_m[0] = 1024;
        o.A[1] = ckv;  o.B[1] = p_M;  o.C[1] = p_kf; o.M[1] = 8192;
        o.sa_m[1] = 256; o.sa_k[1] = 1; o.sb_n[1] = 256; o.sb_k[1] = 1; o.sc_m[1] = 1024;
        o.A[2] = ckv;  o.B[2] = p_Vt; o.C[2] = p_vf; o.M[2] = 8192;
        o.sa_m[2] = 256; o.sa_k[2] = 1; o.sb_n[2] = 256; o.sb_k[2] = 1; o.sc_m[2] = 1024;
        gemm_multi<128><<<dim3(8, 64, 3), thr>>>(o, 1024, 256);
    }

    // ---- flash attention (hs=64), writes y head-slices directly ----
    cudaFuncSetAttribute(flash2, cudaFuncAttributeMaxDynamicSharedMemorySize,
                         FA2_SMEM_BYTES);
    flash2<<<dim3(TT / 128, NH, BB), thr, FA2_SMEM_BYTES>>>(p_qf, p_kf, p_vf, y);
}